// round 8
// baseline (speedup 1.0000x reference)
#include <cuda_runtime.h>
#include <cstdint>

// x[62,8192,128] f32, W[62,256,128] f32, gamma[256], beta[256]
// out[62,8192,256] f32 = LayerNorm(x @ W^T) over the 256 dim.
//
// compute_103a path: tcgen05 kind::tf32 SS-mode, warp-specialized:
//   warps 0-15 : epilogue — single-pass register-resident LDTM (d[64]),
//                4 warps per TMEM subpartition x 64 cols
//   warps 16-17: loaders — cp.async A chunks into 4-slot ring (no reg staging)
//   warp  18   : MMA issuer (M=128,N=256,K=8 dispatches; D double-buffered TMEM)
// Fallback (plain compute_103 PTX pass): cp.async + mma.sync kernel.

#define P_PARTS 62
#define NROWS   8192
#define CIN     128
#define COUT    256
#define BM      128
#define YBLOCKS 16
#define ITERS   4
#define NTHREADS 608
#define EPI_T   512
#define LD_T    64
#define LN_EPS  1e-5f

#if defined(__CUDA_ARCH__) && (defined(__CUDA_ARCH_FEAT_SM103_ALL) || defined(__CUDA_ARCH_FEAT_SM100_ALL) || defined(__CUDA_ARCH_FEAT_SM101_ALL))
#define HAS_TCGEN05 1
#else
#define HAS_TCGEN05 0
#endif

// ---- smem layout (bytes) ----
#define TMEM_PTR_OFF 0
#define MB_CHUNK_FULL(s)  (16 + (s) * 8)    // count 64 (loader cp.async arrives)
#define MB_CHUNK_EMPTY(s) (48 + (s) * 8)    // count 1 (tcgen05.commit)
#define MB_D_FULL(b)      (80 + (b) * 8)    // count 1 (tcgen05.commit)
#define MB_D_EMPTY(b)     (96 + (b) * 8)    // count 512 (epilogue threads)
#define GS_OFF       128
#define BT_OFF       1152
#define PS_OFF       2176     // [2 parity][4 q][128 row] f32 = 4KB
#define PQ_OFF       6272     // 4KB
#define A_OFF        11264    // 4 slots x 16KB (128 rows x 128B, K=32)
#define A_SLOT_BYTES 16384
#define B_OFF        (A_OFF + 4 * A_SLOT_BYTES)   // 4 chunks x 32KB (256 x 128B, K=32)
#define B_CHUNK_BYTES 32768
#define TC_SMEM_BYTES (B_OFF + 4 * B_CHUNK_BYTES) // 207872

// idesc kind::tf32: c=F32(1<<4), a=TF32(2<<7), b=TF32(2<<10), N/8<<17, M/16<<24
#define MMA_IDESC ((1u << 4) | (2u << 7) | (2u << 10) | ((COUT / 8) << 17) | ((BM / 16) << 24))

static constexpr uint64_t SMEM_DESC_BASE_SW128 =
    (uint64_t(2) << 61) | (uint64_t(1) << 46) | (uint64_t(64) << 32) | (uint64_t(1) << 16);
#define MAKE_SMEM_DESC(base_addr) \
    (SMEM_DESC_BASE_SW128 | ((uint64_t)((base_addr) >> 4) & 0x3FFF))
#define SMEM_SWIZZLE_128B(off) ((off) ^ (((off) >> 3) & 0x70))

// ---- fallback constants ----
#define KC      64
#define LDA_F   68
#define LDB_F   132
#define FB_T    512
#define FB_SMEM_BYTES ((COUT * LDB_F + 2 * BM * LDA_F + 128 * 4 * 2 + 256) * 4)
#define SMEM_BYTES (TC_SMEM_BYTES > FB_SMEM_BYTES ? TC_SMEM_BYTES : FB_SMEM_BYTES)

__device__ __forceinline__ uint32_t f2tf32(float f) {
    uint32_t r;
    asm volatile("cvt.rna.tf32.f32 %0, %1;" : "=r"(r) : "f"(f));
    return r;
}
__device__ __forceinline__ uint32_t smem_u32(const void* p) {
    uint32_t a;
    asm("{ .reg .u64 t; cvta.to.shared.u64 t, %1; cvt.u32.u64 %0, t; }" : "=r"(a) : "l"(p));
    return a;
}
__device__ __forceinline__ void cp16s(uint32_t dst_smem, const float* src) {
    asm volatile("cp.async.cg.shared.global [%0], [%1], 16;" :: "r"(dst_smem), "l"(src));
}

#if HAS_TCGEN05
__device__ __forceinline__ uint32_t elect_one() {
    uint32_t pred;
    asm volatile("{ .reg .pred p; elect.sync _|p, 0xFFFFFFFF; selp.b32 %0, 1, 0, p; }" : "=r"(pred));
    return pred;
}
#define MBARRIER_INIT(a, n) \
    asm volatile("mbarrier.init.shared.b64 [%0], %1;" :: "r"((uint32_t)(a)), "r"((uint32_t)(n)) : "memory")
#define MBARRIER_ARRIVE(a) \
    asm volatile("mbarrier.arrive.shared.b64 _, [%0];" :: "r"((uint32_t)(a)) : "memory")
#define CPASYNC_ARRIVE(a) \
    asm volatile("cp.async.mbarrier.arrive.noinc.shared.b64 [%0];" :: "r"((uint32_t)(a)) : "memory")
#define MBAR_WAIT(a, ph) do {                                              \
    uint32_t _m = (uint32_t)(a), _p = (uint32_t)(ph);                      \
    asm volatile(                                                          \
        "{\n\t.reg .pred P1;\n\t"                                          \
        "WL_%=:\n\t"                                                       \
        "mbarrier.try_wait.parity.acquire.cta.shared::cta.b64 P1, [%0], %1, 0x989680;\n\t" \
        "@P1 bra.uni WD_%=;\n\t"                                           \
        "bra.uni WL_%=;\n\t"                                               \
        "WD_%=:\n\t}"                                                      \
        :: "r"(_m), "r"(_p) : "memory");                                   \
} while (0)
#define MBAR_WAIT_RELAXED(a, ph) do {                                      \
    uint32_t _m = (uint32_t)(a), _p = (uint32_t)(ph);                      \
    asm volatile(                                                          \
        "{\n\t.reg .pred P1;\n\t"                                          \
        "WL_%=:\n\t"                                                       \
        "mbarrier.try_wait.parity.relaxed.cta.shared::cta.b64 P1, [%0], %1, 0x989680;\n\t" \
        "@P1 bra.uni WD_%=;\n\t"                                           \
        "bra.uni WL_%=;\n\t"                                               \
        "WD_%=:\n\t}"                                                      \
        :: "r"(_m), "r"(_p) : "memory");                                   \
} while (0)
#define FENCE_ASYNC() asm volatile("fence.proxy.async.shared::cta;" ::: "memory")
#define TCGEN05_ALLOC(sm, n) \
    asm volatile("tcgen05.alloc.cta_group::1.sync.aligned.shared::cta.b32 [%0], %1;" \
                 :: "r"((uint32_t)(sm)), "r"((uint32_t)(n)) : "memory")
#define TCGEN05_DEALLOC(t, n) \
    asm volatile("tcgen05.dealloc.cta_group::1.sync.aligned.b32 %0, %1;" :: "r"(t), "r"((uint32_t)(n)))
#define TCGEN05_RELINQ() \
    asm volatile("tcgen05.relinquish_alloc_permit.cta_group::1.sync.aligned;")
#define TCGEN05_COMMIT(mb) \
    asm volatile("tcgen05.commit.cta_group::1.mbarrier::arrive::one.shared::cluster.b64 [%0];" \
                 :: "r"((uint32_t)(mb)) : "memory")
#define TCGEN05_FENCE_AFTER()  asm volatile("tcgen05.fence::after_thread_sync;" ::: "memory")
#define TCGEN05_FENCE_BEFORE() asm volatile("tcgen05.fence::before_thread_sync;" ::: "memory")
#define TCGEN05_WAIT_LD() asm volatile("tcgen05.wait::ld.sync.aligned;" ::: "memory")

__device__ __forceinline__ void mma_tf32_ss(uint32_t d_tmem, uint64_t a_desc, uint64_t b_desc,
                                            uint32_t idesc, uint32_t enable) {
    asm volatile(
        "{\n\t.reg .pred p;\n\t"
        "setp.ne.u32 p, %4, 0;\n\t"
        "tcgen05.mma.cta_group::1.kind::tf32 [%0], %1, %2, %3, {%5, %5, %5, %5}, p;\n\t}"
        :: "r"(d_tmem), "l"(a_desc), "l"(b_desc), "r"(idesc), "r"(enable), "r"(0u)
        : "memory");
}

#define TCGEN05_LD_X32(r, addr)                                                     \
    asm volatile(                                                                   \
        "tcgen05.ld.sync.aligned.32x32b.x32.b32 "                                   \
        "{%0, %1, %2, %3, %4, %5, %6, %7, "                                         \
        " %8, %9, %10, %11, %12, %13, %14, %15, "                                   \
        " %16, %17, %18, %19, %20, %21, %22, %23, "                                 \
        " %24, %25, %26, %27, %28, %29, %30, %31}, [%32];"                          \
        : "=r"((r)[0]),  "=r"((r)[1]),  "=r"((r)[2]),  "=r"((r)[3]),                \
          "=r"((r)[4]),  "=r"((r)[5]),  "=r"((r)[6]),  "=r"((r)[7]),                \
          "=r"((r)[8]),  "=r"((r)[9]),  "=r"((r)[10]), "=r"((r)[11]),               \
          "=r"((r)[12]), "=r"((r)[13]), "=r"((r)[14]), "=r"((r)[15]),               \
          "=r"((r)[16]), "=r"((r)[17]), "=r"((r)[18]), "=r"((r)[19]),               \
          "=r"((r)[20]), "=r"((r)[21]), "=r"((r)[22]), "=r"((r)[23]),               \
          "=r"((r)[24]), "=r"((r)[25]), "=r"((r)[26]), "=r"((r)[27]),               \
          "=r"((r)[28]), "=r"((r)[29]), "=r"((r)[30]), "=r"((r)[31])                \
        : "r"(addr))

#define NAMED_BAR(id, n) asm volatile("bar.sync %0, %1;" :: "r"(id), "r"(n) : "memory")
#else
__device__ __forceinline__ void cp_commit() {
    asm volatile("cp.async.commit_group;" ::: "memory");
}
template <int N>
__device__ __forceinline__ void cp_wait() {
    asm volatile("cp.async.wait_group %0;" :: "n"(N) : "memory");
}
__device__ __forceinline__ void mma_tf32(float c[4],
                                         uint32_t a0, uint32_t a1, uint32_t a2, uint32_t a3,
                                         uint32_t b0, uint32_t b1) {
    asm volatile(
        "mma.sync.aligned.m16n8k8.row.col.f32.tf32.tf32.f32 "
        "{%0,%1,%2,%3}, {%4,%5,%6,%7}, {%8,%9}, {%0,%1,%2,%3};"
        : "+f"(c[0]), "+f"(c[1]), "+f"(c[2]), "+f"(c[3])
        : "r"(a0), "r"(a1), "r"(a2), "r"(a3), "r"(b0), "r"(b1));
}
#endif

extern __shared__ char smem_raw[];

__global__ void __launch_bounds__(NTHREADS, 1)
fused_gemm_ln(const float* __restrict__ x, const float* __restrict__ W,
              const float* __restrict__ gamma, const float* __restrict__ beta,
              float* __restrict__ out)
{
#if HAS_TCGEN05
    char* smem = smem_raw;
    const uint32_t sb = smem_u32(smem);
    const int tid  = threadIdx.x;
    const int wid  = tid >> 5;
    const int lane = tid & 31;
    const int p    = blockIdx.x;

    if (wid == 18) TCGEN05_ALLOC(sb + TMEM_PTR_OFF, 512);
    if (tid == 0) {
        #pragma unroll
        for (int s = 0; s < 4; ++s) {
            MBARRIER_INIT(sb + MB_CHUNK_FULL(s), LD_T);
            MBARRIER_INIT(sb + MB_CHUNK_EMPTY(s), 1);
        }
        #pragma unroll
        for (int b = 0; b < 2; ++b) {
            MBARRIER_INIT(sb + MB_D_FULL(b), 1);
            MBARRIER_INIT(sb + MB_D_EMPTY(b), EPI_T);
        }
    }

    // ---- prologue: W[p] -> 4 B chunks (K=32 each), tf32(rna) + SW128; gamma/beta ----
    if (tid < EPI_T) {
        const float4* wp = (const float4*)(W + (size_t)p * COUT * CIN);
        #pragma unroll
        for (int i = 0; i < (COUT * CIN / 4) / EPI_T; ++i) {
            int idx = tid + i * EPI_T;           // float4 idx (8192 total)
            int row = idx >> 5;                  // 32 f4 per 128-float row
            int f4  = idx & 31;
            int chunk = f4 >> 3;                 // K=32 chunk
            int f4c   = f4 & 7;
            float4 v = wp[idx];
            uint32_t off = SMEM_SWIZZLE_128B((uint32_t)(row * 128 + f4c * 16));
            float* dst = (float*)(smem + B_OFF + chunk * B_CHUNK_BYTES + off);
            dst[0] = __uint_as_float(f2tf32(v.x));
            dst[1] = __uint_as_float(f2tf32(v.y));
            dst[2] = __uint_as_float(f2tf32(v.z));
            dst[3] = __uint_as_float(f2tf32(v.w));
        }
        if (tid < COUT) {
            ((float*)(smem + GS_OFF))[tid] = gamma[tid];
            ((float*)(smem + BT_OFF))[tid] = beta[tid];
        }
    }
    FENCE_ASYNC();
    __syncthreads();

    uint32_t tmem_base;
    asm volatile("ld.shared.b32 %0, [%1];" : "=r"(tmem_base) : "r"(sb + TMEM_PTR_OFF));

    const float* xp = x + (size_t)p * NROWS * CIN;

    if (wid == 16 || wid == 17) {
        // =================== loader warps (cp.async, no reg staging) ===================
        const int ltid = tid - EPI_T;            // 0..63
        int phase = 1;
        int chunk_idx = 0;
        #pragma unroll 1
        for (int it = 0; it < ITERS; ++it) {
            const int m0 = (blockIdx.y + YBLOCKS * it) * BM;
            #pragma unroll 1
            for (int kc = 0; kc < 4; ++kc) {
                const int s = chunk_idx & 3;
                MBAR_WAIT(sb + MB_CHUNK_EMPTY(s), phase);
                const uint32_t abase = sb + A_OFF + s * A_SLOT_BYTES;
                #pragma unroll
                for (int i = 0; i < 16; ++i) {
                    int idx = ltid + i * LD_T;   // f4 index within chunk (1024 total)
                    int row = idx >> 3;
                    int f4  = idx & 7;
                    uint32_t off = SMEM_SWIZZLE_128B((uint32_t)(row * 128 + f4 * 16));
                    cp16s(abase + off, xp + (size_t)(m0 + row) * CIN + kc * 32 + f4 * 4);
                }
                CPASYNC_ARRIVE(sb + MB_CHUNK_FULL(s));
                ++chunk_idx;
                if ((chunk_idx & 3) == 0) phase ^= 1;
            }
        }
    } else if (wid == 18) {
        // =================== MMA warp ===================
        if (elect_one()) {
            int full_ph = 0, dph = 1, chunk_idx = 0;
            #pragma unroll 1
            for (int it = 0; it < ITERS; ++it) {
                const int b = it & 1;
                MBAR_WAIT_RELAXED(sb + MB_D_EMPTY(b), dph);
                const uint32_t dt = tmem_base + b * 256;
                #pragma unroll 1
                for (int kc = 0; kc < 4; ++kc) {
                    const int s = chunk_idx & 3;
                    MBAR_WAIT_RELAXED(sb + MB_CHUNK_FULL(s), full_ph);
                    FENCE_ASYNC();   // cp.async writes -> async proxy (tcgen05) visibility
                    uint64_t a_base = MAKE_SMEM_DESC(sb + A_OFF + s * A_SLOT_BYTES);
                    uint64_t b_base = MAKE_SMEM_DESC(sb + B_OFF + kc * B_CHUNK_BYTES);
                    #pragma unroll
                    for (int ks = 0; ks < 4; ++ks) {
                        mma_tf32_ss(dt, a_base + ks * 2, b_base + ks * 2,
                                    MMA_IDESC, (uint32_t)(kc | ks));
                    }
                    TCGEN05_COMMIT(sb + MB_CHUNK_EMPTY(s));
                    ++chunk_idx;
                    if ((chunk_idx & 3) == 0) full_ph ^= 1;
                }
                TCGEN05_COMMIT(sb + MB_D_FULL(b));
                if (b == 1) dph ^= 1;
            }
        }
    } else {
        // =================== epilogue warps (0-15), single pass ===================
        const int sub = wid & 3;                 // TMEM subpartition -> rows sub*32+lane
        const int q   = wid >> 2;                // column quarter (64 cols)
        const int row = sub * 32 + lane;
        float* Ps = (float*)(smem + PS_OFF);
        float* Pq = (float*)(smem + PQ_OFF);
        const float* Gs = (const float*)(smem + GS_OFF);
        const float* Bt = (const float*)(smem + BT_OFF);
        int dph = 0;
        #pragma unroll 1
        for (int it = 0; it < ITERS; ++it) {
            const int b = it & 1;
            MBAR_WAIT(sb + MB_D_FULL(b), dph);
            TCGEN05_FENCE_AFTER();
            const uint32_t dt = tmem_base + b * 256 + q * 64;

            uint32_t d[64];
            TCGEN05_LD_X32(d, dt);
            TCGEN05_LD_X32(d + 32, dt + 32);
            TCGEN05_WAIT_LD();

            float sv = 0.f, qv = 0.f;
            #pragma unroll
            for (int j = 0; j < 64; ++j) {
                float f = __uint_as_float(d[j]);
                sv += f;
                qv += f * f;
            }
            Ps[(b * 4 + q) * 128 + row] = sv;
            Pq[(b * 4 + q) * 128 + row] = qv;
            NAMED_BAR(1, EPI_T);
            float tot = Ps[(b * 4 + 0) * 128 + row] + Ps[(b * 4 + 1) * 128 + row]
                      + Ps[(b * 4 + 2) * 128 + row] + Ps[(b * 4 + 3) * 128 + row];
            float qt  = Pq[(b * 4 + 0) * 128 + row] + Pq[(b * 4 + 1) * 128 + row]
                      + Pq[(b * 4 + 2) * 128 + row] + Pq[(b * 4 + 3) * 128 + row];
            float mu  = tot * (1.0f / COUT);
            float var = qt * (1.0f / COUT) - mu * mu;
            float rs  = rsqrtf(var + LN_EPS);

            const int m0 = (blockIdx.y + YBLOCKS * it) * BM;
            float* orow = out + ((size_t)p * NROWS + m0 + row) * COUT + q * 64;
            #pragma unroll
            for (int k = 0; k < 8; ++k) {
                float4 g4 = *(const float4*)&Gs[q * 64 + k * 8];
                float4 g5 = *(const float4*)&Gs[q * 64 + k * 8 + 4];
                float4 b4 = *(const float4*)&Bt[q * 64 + k * 8];
                float4 b5 = *(const float4*)&Bt[q * 64 + k * 8 + 4];
                float4 o0, o1;
                o0.x = (__uint_as_float(d[k*8+0]) - mu) * rs * g4.x + b4.x;
                o0.y = (__uint_as_float(d[k*8+1]) - mu) * rs * g4.y + b4.y;
                o0.z = (__uint_as_float(d[k*8+2]) - mu) * rs * g4.z + b4.z;
                o0.w = (__uint_as_float(d[k*8+3]) - mu) * rs * g4.w + b4.w;
                o1.x = (__uint_as_float(d[k*8+4]) - mu) * rs * g5.x + b5.x;
                o1.y = (__uint_as_float(d[k*8+5]) - mu) * rs * g5.y + b5.y;
                o1.z = (__uint_as_float(d[k*8+6]) - mu) * rs * g5.z + b5.z;
                o1.w = (__uint_as_float(d[k*8+7]) - mu) * rs * g5.w + b5.w;
                *(float4*)&orow[k * 8]     = o0;
                *(float4*)&orow[k * 8 + 4] = o1;
            }
            TCGEN05_FENCE_BEFORE();
            MBARRIER_ARRIVE(sb + MB_D_EMPTY(b));
            if (b == 1) dph ^= 1;
        }
    }

    __syncthreads();
    if (wid == 18) {
        TCGEN05_RELINQ();
        TCGEN05_DEALLOC(tmem_base, 512);
    }
#else
    // ======================= fallback: cp.async + mma.sync (512 threads) =======================
    if (threadIdx.x >= FB_T) return;
    float* smem = (float*)smem_raw;
    float* Bs = smem;
    float* A0 = Bs + COUT * LDB_F;
    float* A1 = A0 + BM * LDA_F;
    float* Ps = A1 + BM * LDA_F;
    float* Pq = Ps + 128 * 4;
    float* Mu = Pq + 128 * 4;
    float* Rs = Mu + 128;

    const int tid  = threadIdx.x;
    const int warp = tid >> 5;
    const int lane = tid & 31;
    const int wm = warp >> 2;
    const int wn = warp & 3;
    const int g  = lane >> 2;
    const int t  = lane & 3;
    const int p  = blockIdx.x;

    const float* xp = x + (size_t)p * NROWS * CIN;

    auto issue_chunk = [&](float* buf, int m0, int kc) {
        #pragma unroll
        for (int ii = 0; ii < 4; ++ii) {
            int idx = tid + ii * FB_T;
            int row = idx >> 4;
            int c4  = idx & 15;
            cp16s((uint32_t)__cvta_generic_to_shared(&buf[row * LDA_F + c4 * 4]),
                  xp + ((size_t)(m0 + row)) * CIN + kc * KC + c4 * 4);
        }
        cp_commit();
    };

    {
        const int m0 = blockIdx.y * BM;
        issue_chunk(A0, m0, 0);
        issue_chunk(A1, m0, 1);
    }
    {
        const float4* wp = (const float4*)(W + (size_t)p * COUT * CIN);
        #pragma unroll
        for (int ii = 0; ii < (COUT * CIN / 4) / FB_T; ++ii) {
            int idx = tid + ii * FB_T;
            int row = idx >> 5;
            int c4  = idx & 31;
            float4 v = wp[idx];
            float* dst = &Bs[row * LDB_F + c4 * 4];
            dst[0] = __uint_as_float(f2tf32(v.x));
            dst[1] = __uint_as_float(f2tf32(v.y));
            dst[2] = __uint_as_float(f2tf32(v.z));
            dst[3] = __uint_as_float(f2tf32(v.w));
        }
    }

    #pragma unroll
    for (int it = 0; it < ITERS; ++it) {
        const int m0  = (blockIdx.y + YBLOCKS * it) * BM;
        const int m0n = (blockIdx.y + YBLOCKS * (it + 1)) * BM;

        float c[2][8][4];
        #pragma unroll
        for (int i = 0; i < 2; ++i)
            #pragma unroll
            for (int j = 0; j < 8; ++j)
                #pragma unroll
                for (int qq = 0; qq < 4; ++qq) c[i][j][qq] = 0.0f;

        auto half_mma = [&](const float* __restrict__ Ab, int koff) {
            #pragma unroll
            for (int kk = 0; kk < 8; ++kk) {
                const int k0 = kk * 8;
                const int kb = koff + k0;
                uint32_t a[2][4];
                #pragma unroll
                for (int i = 0; i < 2; ++i) {
                    int r = wm * 32 + i * 16 + g;
                    a[i][0] = f2tf32(Ab[r * LDA_F + k0 + t]);
                    a[i][1] = f2tf32(Ab[(r + 8) * LDA_F + k0 + t]);
                    a[i][2] = f2tf32(Ab[r * LDA_F + k0 + t + 4]);
                    a[i][3] = f2tf32(Ab[(r + 8) * LDA_F + k0 + t + 4]);
                }
                #pragma unroll
                for (int j = 0; j < 8; ++j) {
                    int d = wn * 64 + j * 8 + g;
                    uint32_t b0 = __float_as_uint(Bs[d * LDB_F + kb + t]);
                    uint32_t b1 = __float_as_uint(Bs[d * LDB_F + kb + t + 4]);
                    mma_tf32(c[0][j], a[0][0], a[0][1], a[0][2], a[0][3], b0, b1);
                    mma_tf32(c[1][j], a[1][0], a[1][1], a[1][2], a[1][3], b0, b1);
                }
            }
        };

        cp_wait<1>();
        __syncthreads();
        half_mma(A0, 0);
        __syncthreads();
        if (it < ITERS - 1) issue_chunk(A0, m0n, 0);

        if (it < ITERS - 1) cp_wait<1>(); else cp_wait<0>();
        __syncthreads();
        half_mma(A1, 64);

        float sacc[2][2] = {{0.f, 0.f}, {0.f, 0.f}};
        float qacc[2][2] = {{0.f, 0.f}, {0.f, 0.f}};
        #pragma unroll
        for (int i = 0; i < 2; ++i)
            #pragma unroll
            for (int j = 0; j < 8; ++j) {
                const float* cc = c[i][j];
                sacc[i][0] += cc[0] + cc[1];
                qacc[i][0] += cc[0] * cc[0] + cc[1] * cc[1];
                sacc[i][1] += cc[2] + cc[3];
                qacc[i][1] += cc[2] * cc[2] + cc[3] * cc[3];
            }
        #pragma unroll
        for (int i = 0; i < 2; ++i)
            #pragma unroll
            for (int s = 0; s < 2; ++s) {
                float sv = sacc[i][s], qv = qacc[i][s];
                sv += __shfl_xor_sync(0xffffffffu, sv, 1);
                sv += __shfl_xor_sync(0xffffffffu, sv, 2);
                qv += __shfl_xor_sync(0xffffffffu, qv, 1);
                qv += __shfl_xor_sync(0xffffffffu, qv, 2);
                if (t == 0) {
                    int r = wm * 32 + i * 16 + s * 8 + g;
                    Ps[r * 4 + wn] = sv;
                    Pq[r * 4 + wn] = qv;
                }
            }
        __syncthreads();
        if (it < ITERS - 1) issue_chunk(A1, m0n, 1);

        if (tid < BM) {
            float sv = Ps[tid * 4 + 0] + Ps[tid * 4 + 1] + Ps[tid * 4 + 2] + Ps[tid * 4 + 3];
            float qv = Pq[tid * 4 + 0] + Pq[tid * 4 + 1] + Pq[tid * 4 + 2] + Pq[tid * 4 + 3];
            float mu  = sv * (1.0f / COUT);
            float var = qv * (1.0f / COUT) - mu * mu;
            Mu[tid] = mu;
            Rs[tid] = rsqrtf(var + LN_EPS);
        }
        __syncthreads();

        const size_t obase = ((size_t)p * NROWS + m0) * COUT;
        #pragma unroll
        for (int i = 0; i < 2; ++i) {
            int r0 = wm * 32 + i * 16 + g;
            float mu0 = Mu[r0],     rs0 = Rs[r0];
            float mu1 = Mu[r0 + 8], rs1 = Rs[r0 + 8];
            #pragma unroll
            for (int j = 0; j < 8; ++j) {
                int col = wn * 64 + j * 8 + 2 * t;
                float g0 = __ldg(&gamma[col]), g1 = __ldg(&gamma[col + 1]);
                float b0 = __ldg(&beta[col]),  b1 = __ldg(&beta[col + 1]);
                float2 v0, v1;
                v0.x = (c[i][j][0] - mu0) * rs0 * g0 + b0;
                v0.y = (c[i][j][1] - mu0) * rs0 * g1 + b1;
                v1.x = (c[i][j][2] - mu1) * rs1 * g0 + b0;
                v1.y = (c[i][j][3] - mu1) * rs1 * g1 + b1;
                *(float2*)&out[obase + (size_t)r0 * COUT + col]       = v0;
                *(float2*)&out[obase + (size_t)(r0 + 8) * COUT + col] = v1;
            }
        }
    }
#endif
}

extern "C" void kernel_launch(void* const* d_in, const int* in_sizes, int n_in,
                              void* d_out, int out_size)
{
    const float* x     = (const float*)d_in[0];
    const float* W     = (const float*)d_in[1];
    const float* gamma = (const float*)d_in[2];
    const float* beta  = (const float*)d_in[3];
    float* out = (float*)d_out;

    cudaFuncSetAttribute(fused_gemm_ln,
                         cudaFuncAttributeMaxDynamicSharedMemorySize, (int)SMEM_BYTES);

    dim3 grid(P_PARTS, YBLOCKS);
    fused_gemm_ln<<<grid, NTHREADS, (int)SMEM_BYTES>>>(x, W, gamma, beta, out);
}

// round 9
// speedup vs baseline: 1.2983x; 1.2983x over previous
#include <cuda_runtime.h>
#include <cstdint>

// x[62,8192,128] f32, W[62,256,128] f32, gamma[256], beta[256]
// out[62,8192,256] f32 = LayerNorm(x @ W^T) over the 256 dim.
//
// compute_103a path: tcgen05 kind::tf32 SS-mode, 2 CTAs/SM (104KB smem, 256 TMEM
// cols per CTA). Both A and B(=W) streamed through 2-slot cp.async rings; W
// re-reads are L2 hits. Warps: 0-7 epilogue (2-pass streaming LDTM),
// 8-11 loaders, 12 MMA issuer.
// Fallback (plain compute_103 PTX pass): compiles only, never runs on sm_103a.

#define P_PARTS 62
#define NROWS   8192
#define CIN     128
#define COUT    256
#define BM      128
#define YBLOCKS 32
#define ITERS   2
#define NTHREADS 416
#define EPI_T   256
#define LD_T    128
#define LN_EPS  1e-5f

#if defined(__CUDA_ARCH__) && (defined(__CUDA_ARCH_FEAT_SM103_ALL) || defined(__CUDA_ARCH_FEAT_SM100_ALL) || defined(__CUDA_ARCH_FEAT_SM101_ALL))
#define HAS_TCGEN05 1
#else
#define HAS_TCGEN05 0
#endif

// ---- smem layout (bytes) ----
#define TMEM_PTR_OFF 0
#define MB_A_FULL(s)  (16 + (s) * 8)     // count 128 (loader cp.async arrives)
#define MB_A_EMPTY(s) (32 + (s) * 8)     // count 1 (tcgen05.commit)
#define MB_B_FULL(s)  (48 + (s) * 8)     // count 128
#define MB_B_EMPTY(s) (64 + (s) * 8)     // count 1 (commit)
#define MB_D_FULL     80                 // count 1 (commit)
#define MB_D_EMPTY    88                 // count 256 (epilogue threads)
#define GS_OFF       128
#define BT_OFF       1152
#define PS_OFF       2176                // [2 parity][128 row][2 half] = 2KB
#define PQ_OFF       4224                // 2KB
#define A_OFF        8192                // 2 slots x 16KB (128 rows x 128B, K=32)
#define A_SLOT_BYTES 16384
#define B_OFF        (A_OFF + 2 * A_SLOT_BYTES)   // 2 slots x 32KB (256 x 128B, K=32)
#define B_SLOT_BYTES 32768
#define TC_SMEM_BYTES (B_OFF + 2 * B_SLOT_BYTES)  // 106496

// idesc kind::tf32: c=F32(1<<4), a=TF32(2<<7), b=TF32(2<<10), N/8<<17, M/16<<24
#define MMA_IDESC ((1u << 4) | (2u << 7) | (2u << 10) | ((COUT / 8) << 17) | ((BM / 16) << 24))

static constexpr uint64_t SMEM_DESC_BASE_SW128 =
    (uint64_t(2) << 61) | (uint64_t(1) << 46) | (uint64_t(64) << 32) | (uint64_t(1) << 16);
#define MAKE_SMEM_DESC(base_addr) \
    (SMEM_DESC_BASE_SW128 | ((uint64_t)((base_addr) >> 4) & 0x3FFF))
#define SMEM_SWIZZLE_128B(off) ((off) ^ (((off) >> 3) & 0x70))

// ---- fallback constants (compile-only on plain compute_103) ----
#define KC      64
#define LDA_F   68
#define LDB_F   132
#define FB_T    512

__device__ __forceinline__ uint32_t f2tf32(float f) {
    uint32_t r;
    asm volatile("cvt.rna.tf32.f32 %0, %1;" : "=r"(r) : "f"(f));
    return r;
}
__device__ __forceinline__ uint32_t smem_u32(const void* p) {
    uint32_t a;
    asm("{ .reg .u64 t; cvta.to.shared.u64 t, %1; cvt.u32.u64 %0, t; }" : "=r"(a) : "l"(p));
    return a;
}
__device__ __forceinline__ void cp16s(uint32_t dst_smem, const float* src) {
    asm volatile("cp.async.cg.shared.global [%0], [%1], 16;" :: "r"(dst_smem), "l"(src));
}

#if HAS_TCGEN05
__device__ __forceinline__ uint32_t elect_one() {
    uint32_t pred;
    asm volatile("{ .reg .pred p; elect.sync _|p, 0xFFFFFFFF; selp.b32 %0, 1, 0, p; }" : "=r"(pred));
    return pred;
}
#define MBARRIER_INIT(a, n) \
    asm volatile("mbarrier.init.shared.b64 [%0], %1;" :: "r"((uint32_t)(a)), "r"((uint32_t)(n)) : "memory")
#define MBARRIER_ARRIVE(a) \
    asm volatile("mbarrier.arrive.shared.b64 _, [%0];" :: "r"((uint32_t)(a)) : "memory")
#define CPASYNC_ARRIVE(a) \
    asm volatile("cp.async.mbarrier.arrive.noinc.shared.b64 [%0];" :: "r"((uint32_t)(a)) : "memory")
#define MBAR_WAIT(a, ph) do {                                              \
    uint32_t _m = (uint32_t)(a), _p = (uint32_t)(ph);                      \
    asm volatile(                                                          \
        "{\n\t.reg .pred P1;\n\t"                                          \
        "WL_%=:\n\t"                                                       \
        "mbarrier.try_wait.parity.acquire.cta.shared::cta.b64 P1, [%0], %1, 0x989680;\n\t" \
        "@P1 bra.uni WD_%=;\n\t"                                           \
        "bra.uni WL_%=;\n\t"                                               \
        "WD_%=:\n\t}"                                                      \
        :: "r"(_m), "r"(_p) : "memory");                                   \
} while (0)
#define MBAR_WAIT_RELAXED(a, ph) do {                                      \
    uint32_t _m = (uint32_t)(a), _p = (uint32_t)(ph);                      \
    asm volatile(                                                          \
        "{\n\t.reg .pred P1;\n\t"                                          \
        "WL_%=:\n\t"                                                       \
        "mbarrier.try_wait.parity.relaxed.cta.shared::cta.b64 P1, [%0], %1, 0x989680;\n\t" \
        "@P1 bra.uni WD_%=;\n\t"                                           \
        "bra.uni WL_%=;\n\t"                                               \
        "WD_%=:\n\t}"                                                      \
        :: "r"(_m), "r"(_p) : "memory");                                   \
} while (0)
#define FENCE_ASYNC() asm volatile("fence.proxy.async.shared::cta;" ::: "memory")
#define TCGEN05_ALLOC(sm, n) \
    asm volatile("tcgen05.alloc.cta_group::1.sync.aligned.shared::cta.b32 [%0], %1;" \
                 :: "r"((uint32_t)(sm)), "r"((uint32_t)(n)) : "memory")
#define TCGEN05_DEALLOC(t, n) \
    asm volatile("tcgen05.dealloc.cta_group::1.sync.aligned.b32 %0, %1;" :: "r"(t), "r"((uint32_t)(n)))
#define TCGEN05_RELINQ() \
    asm volatile("tcgen05.relinquish_alloc_permit.cta_group::1.sync.aligned;")
#define TCGEN05_COMMIT(mb) \
    asm volatile("tcgen05.commit.cta_group::1.mbarrier::arrive::one.shared::cluster.b64 [%0];" \
                 :: "r"((uint32_t)(mb)) : "memory")
#define TCGEN05_FENCE_AFTER()  asm volatile("tcgen05.fence::after_thread_sync;" ::: "memory")
#define TCGEN05_FENCE_BEFORE() asm volatile("tcgen05.fence::before_thread_sync;" ::: "memory")
#define TCGEN05_WAIT_LD() asm volatile("tcgen05.wait::ld.sync.aligned;" ::: "memory")

__device__ __forceinline__ void mma_tf32_ss(uint32_t d_tmem, uint64_t a_desc, uint64_t b_desc,
                                            uint32_t idesc, uint32_t enable) {
    asm volatile(
        "{\n\t.reg .pred p;\n\t"
        "setp.ne.u32 p, %4, 0;\n\t"
        "tcgen05.mma.cta_group::1.kind::tf32 [%0], %1, %2, %3, {%5, %5, %5, %5}, p;\n\t}"
        :: "r"(d_tmem), "l"(a_desc), "l"(b_desc), "r"(idesc), "r"(enable), "r"(0u)
        : "memory");
}

#define TCGEN05_LD_X32(r, addr)                                                     \
    asm volatile(                                                                   \
        "tcgen05.ld.sync.aligned.32x32b.x32.b32 "                                   \
        "{%0, %1, %2, %3, %4, %5, %6, %7, "                                         \
        " %8, %9, %10, %11, %12, %13, %14, %15, "                                   \
        " %16, %17, %18, %19, %20, %21, %22, %23, "                                 \
        " %24, %25, %26, %27, %28, %29, %30, %31}, [%32];"                          \
        : "=r"((r)[0]),  "=r"((r)[1]),  "=r"((r)[2]),  "=r"((r)[3]),                \
          "=r"((r)[4]),  "=r"((r)[5]),  "=r"((r)[6]),  "=r"((r)[7]),                \
          "=r"((r)[8]),  "=r"((r)[9]),  "=r"((r)[10]), "=r"((r)[11]),               \
          "=r"((r)[12]), "=r"((r)[13]), "=r"((r)[14]), "=r"((r)[15]),               \
          "=r"((r)[16]), "=r"((r)[17]), "=r"((r)[18]), "=r"((r)[19]),               \
          "=r"((r)[20]), "=r"((r)[21]), "=r"((r)[22]), "=r"((r)[23]),               \
          "=r"((r)[24]), "=r"((r)[25]), "=r"((r)[26]), "=r"((r)[27]),               \
          "=r"((r)[28]), "=r"((r)[29]), "=r"((r)[30]), "=r"((r)[31])                \
        : "r"(addr))

#define NAMED_BAR(id, n) asm volatile("bar.sync %0, %1;" :: "r"(id), "r"(n) : "memory")
#else
__device__ __forceinline__ void cp_commit() {
    asm volatile("cp.async.commit_group;" ::: "memory");
}
template <int N>
__device__ __forceinline__ void cp_wait() {
    asm volatile("cp.async.wait_group %0;" :: "n"(N) : "memory");
}
__device__ __forceinline__ void mma_tf32(float c[4],
                                         uint32_t a0, uint32_t a1, uint32_t a2, uint32_t a3,
                                         uint32_t b0, uint32_t b1) {
    asm volatile(
        "mma.sync.aligned.m16n8k8.row.col.f32.tf32.tf32.f32 "
        "{%0,%1,%2,%3}, {%4,%5,%6,%7}, {%8,%9}, {%0,%1,%2,%3};"
        : "+f"(c[0]), "+f"(c[1]), "+f"(c[2]), "+f"(c[3])
        : "r"(a0), "r"(a1), "r"(a2), "r"(a3), "r"(b0), "r"(b1));
}
#endif

extern __shared__ char smem_raw[];

__global__ void __launch_bounds__(NTHREADS, 2)
fused_gemm_ln(const float* __restrict__ x, const float* __restrict__ W,
              const float* __restrict__ gamma, const float* __restrict__ beta,
              float* __restrict__ out)
{
#if HAS_TCGEN05
    char* smem = smem_raw;
    const uint32_t sb = smem_u32(smem);
    const int tid  = threadIdx.x;
    const int wid  = tid >> 5;
    const int lane = tid & 31;
    const int p    = blockIdx.x;

    if (wid == 12) TCGEN05_ALLOC(sb + TMEM_PTR_OFF, 256);
    if (tid == 0) {
        #pragma unroll
        for (int s = 0; s < 2; ++s) {
            MBARRIER_INIT(sb + MB_A_FULL(s), LD_T);
            MBARRIER_INIT(sb + MB_A_EMPTY(s), 1);
            MBARRIER_INIT(sb + MB_B_FULL(s), LD_T);
            MBARRIER_INIT(sb + MB_B_EMPTY(s), 1);
        }
        MBARRIER_INIT(sb + MB_D_FULL, 1);
        MBARRIER_INIT(sb + MB_D_EMPTY, EPI_T);
    }
    if (tid < COUT) {
        ((float*)(smem + GS_OFF))[tid] = gamma[tid];
        ((float*)(smem + BT_OFF))[tid] = beta[tid];
    }
    __syncthreads();

    uint32_t tmem_base;
    asm volatile("ld.shared.b32 %0, [%1];" : "=r"(tmem_base) : "r"(sb + TMEM_PTR_OFF));

    const float* xp = x + (size_t)p * NROWS * CIN;
    const float* wp = W + (size_t)p * COUT * CIN;

    if (wid >= 8 && wid < 12) {
        // =================== loader warps (A + B cp.async rings) ===================
        const int ltid = tid - EPI_T;            // 0..127
        #pragma unroll 1
        for (int c = 0; c < ITERS * 4; ++c) {
            const int it = c >> 2;
            const int kc = c & 3;
            const int s  = c & 1;
            const int k  = c >> 1;               // per-slot use count
            const int pe = 1 ^ (k & 1);          // producer-reclaim parity
            const int m0 = (blockIdx.y + YBLOCKS * it) * BM;

            MBAR_WAIT(sb + MB_A_EMPTY(s), pe);
            {
                const uint32_t abase = sb + A_OFF + s * A_SLOT_BYTES;
                #pragma unroll
                for (int i = 0; i < 8; ++i) {
                    int idx = ltid + i * LD_T;   // 0..1023 f4
                    int row = idx >> 3;
                    int f4  = idx & 7;
                    uint32_t off = SMEM_SWIZZLE_128B((uint32_t)(row * 128 + f4 * 16));
                    cp16s(abase + off, xp + (size_t)(m0 + row) * CIN + kc * 32 + f4 * 4);
                }
                CPASYNC_ARRIVE(sb + MB_A_FULL(s));
            }
            MBAR_WAIT(sb + MB_B_EMPTY(s), pe);
            {
                const uint32_t bbase = sb + B_OFF + s * B_SLOT_BYTES;
                #pragma unroll
                for (int i = 0; i < 16; ++i) {
                    int idx = ltid + i * LD_T;   // 0..2047 f4
                    int row = idx >> 3;          // 0..255
                    int f4  = idx & 7;
                    uint32_t off = SMEM_SWIZZLE_128B((uint32_t)(row * 128 + f4 * 16));
                    cp16s(bbase + off, wp + (size_t)row * CIN + kc * 32 + f4 * 4);
                }
                CPASYNC_ARRIVE(sb + MB_B_FULL(s));
            }
        }
    } else if (wid == 12) {
        // =================== MMA warp ===================
        if (elect_one()) {
            #pragma unroll 1
            for (int it = 0; it < ITERS; ++it) {
                MBAR_WAIT_RELAXED(sb + MB_D_EMPTY, 1 ^ (it & 1));
                #pragma unroll 1
                for (int kc = 0; kc < 4; ++kc) {
                    const int c = it * 4 + kc;
                    const int s = c & 1;
                    const int pf = (c >> 1) & 1;     // consumer parity
                    MBAR_WAIT_RELAXED(sb + MB_A_FULL(s), pf);
                    MBAR_WAIT_RELAXED(sb + MB_B_FULL(s), pf);
                    FENCE_ASYNC();   // cp.async writes -> async-proxy visibility
                    uint64_t a_base = MAKE_SMEM_DESC(sb + A_OFF + s * A_SLOT_BYTES);
                    uint64_t b_base = MAKE_SMEM_DESC(sb + B_OFF + s * B_SLOT_BYTES);
                    #pragma unroll
                    for (int ks = 0; ks < 4; ++ks) {
                        mma_tf32_ss(tmem_base, a_base + ks * 2, b_base + ks * 2,
                                    MMA_IDESC, (uint32_t)(kc | ks));
                    }
                    TCGEN05_COMMIT(sb + MB_A_EMPTY(s));
                    TCGEN05_COMMIT(sb + MB_B_EMPTY(s));
                }
                TCGEN05_COMMIT(sb + MB_D_FULL);
            }
        }
    } else {
        // =================== epilogue warps (0-7), streaming 2-pass ===================
        const int h   = wid >> 2;                // column half (128 cols)
        const int sub = wid & 3;                 // TMEM subpartition
        const int row = sub * 32 + lane;
        float* Ps = (float*)(smem + PS_OFF);
        float* Pq = (float*)(smem + PQ_OFF);
        const float* Gs = (const float*)(smem + GS_OFF);
        const float* Bt = (const float*)(smem + BT_OFF);
        #pragma unroll 1
        for (int it = 0; it < ITERS; ++it) {
            const int par = it & 1;
            MBAR_WAIT(sb + MB_D_FULL, par);
            TCGEN05_FENCE_AFTER();
            const uint32_t dt = tmem_base + h * 128;

            // pass 1: stats
            float sv = 0.f, qv = 0.f;
            #pragma unroll 1
            for (int st = 0; st < 4; ++st) {
                uint32_t d[32];
                TCGEN05_LD_X32(d, dt + st * 32);
                TCGEN05_WAIT_LD();
                #pragma unroll
                for (int j = 0; j < 32; ++j) {
                    float f = __uint_as_float(d[j]);
                    sv += f;
                    qv += f * f;
                }
            }
            Ps[par * 256 + row * 2 + h] = sv;
            Pq[par * 256 + row * 2 + h] = qv;
            NAMED_BAR(1, EPI_T);
            float tot = Ps[par * 256 + row * 2] + Ps[par * 256 + row * 2 + 1];
            float qt  = Pq[par * 256 + row * 2] + Pq[par * 256 + row * 2 + 1];
            float mu  = tot * (1.0f / COUT);
            float var = qt * (1.0f / COUT) - mu * mu;
            float rs  = rsqrtf(var + LN_EPS);

            // pass 2: normalize + store
            const int m0 = (blockIdx.y + YBLOCKS * it) * BM;
            float* orow = out + ((size_t)p * NROWS + m0 + row) * COUT + h * 128;
            #pragma unroll 1
            for (int st = 0; st < 4; ++st) {
                uint32_t d[32];
                TCGEN05_LD_X32(d, dt + st * 32);
                TCGEN05_WAIT_LD();
                const int cb = h * 128 + st * 32;
                #pragma unroll
                for (int k = 0; k < 4; ++k) {
                    float4 g4 = *(const float4*)&Gs[cb + k * 8];
                    float4 g5 = *(const float4*)&Gs[cb + k * 8 + 4];
                    float4 b4 = *(const float4*)&Bt[cb + k * 8];
                    float4 b5 = *(const float4*)&Bt[cb + k * 8 + 4];
                    float4 o0, o1;
                    o0.x = (__uint_as_float(d[k*8+0]) - mu) * rs * g4.x + b4.x;
                    o0.y = (__uint_as_float(d[k*8+1]) - mu) * rs * g4.y + b4.y;
                    o0.z = (__uint_as_float(d[k*8+2]) - mu) * rs * g4.z + b4.z;
                    o0.w = (__uint_as_float(d[k*8+3]) - mu) * rs * g4.w + b4.w;
                    o1.x = (__uint_as_float(d[k*8+4]) - mu) * rs * g5.x + b5.x;
                    o1.y = (__uint_as_float(d[k*8+5]) - mu) * rs * g5.y + b5.y;
                    o1.z = (__uint_as_float(d[k*8+6]) - mu) * rs * g5.z + b5.z;
                    o1.w = (__uint_as_float(d[k*8+7]) - mu) * rs * g5.w + b5.w;
                    *(float4*)&orow[st * 32 + k * 8]     = o0;
                    *(float4*)&orow[st * 32 + k * 8 + 4] = o1;
                }
            }
            TCGEN05_FENCE_BEFORE();
            MBARRIER_ARRIVE(sb + MB_D_EMPTY);
        }
    }

    __syncthreads();
    if (wid == 12) {
        TCGEN05_RELINQ();
        TCGEN05_DEALLOC(tmem_base, 256);
    }
#else
    // ============ fallback: cp.async + mma.sync (compile-only on compute_103) ============
    if (threadIdx.x >= FB_T) return;
    float* smem = (float*)smem_raw;
    float* Bs = smem;
    float* A0 = Bs + COUT * LDB_F;
    float* A1 = A0 + BM * LDA_F;
    float* Ps = A1 + BM * LDA_F;
    float* Pq = Ps + 128 * 4;
    float* Mu = Pq + 128 * 4;
    float* Rs = Mu + 128;

    const int tid  = threadIdx.x;
    const int warp = tid >> 5;
    const int lane = tid & 31;
    const int wm = warp >> 2;
    const int wn = warp & 3;
    const int g  = lane >> 2;
    const int t  = lane & 3;
    const int p  = blockIdx.x;

    const float* xp = x + (size_t)p * NROWS * CIN;

    auto issue_chunk = [&](float* buf, int m0, int kc) {
        #pragma unroll
        for (int ii = 0; ii < 4; ++ii) {
            int idx = tid + ii * FB_T;
            int row = idx >> 4;
            int c4  = idx & 15;
            cp16s((uint32_t)__cvta_generic_to_shared(&buf[row * LDA_F + c4 * 4]),
                  xp + ((size_t)(m0 + row)) * CIN + kc * KC + c4 * 4);
        }
        cp_commit();
    };

    {
        const int m0 = blockIdx.y * BM;
        issue_chunk(A0, m0, 0);
        issue_chunk(A1, m0, 1);
    }
    {
        const float4* wp4 = (const float4*)(W + (size_t)p * COUT * CIN);
        #pragma unroll
        for (int ii = 0; ii < (COUT * CIN / 4) / FB_T; ++ii) {
            int idx = tid + ii * FB_T;
            int row = idx >> 5;
            int c4  = idx & 31;
            float4 v = wp4[idx];
            float* dst = &Bs[row * LDB_F + c4 * 4];
            dst[0] = __uint_as_float(f2tf32(v.x));
            dst[1] = __uint_as_float(f2tf32(v.y));
            dst[2] = __uint_as_float(f2tf32(v.z));
            dst[3] = __uint_as_float(f2tf32(v.w));
        }
    }

    #pragma unroll
    for (int it = 0; it < 2; ++it) {
        const int m0  = (blockIdx.y + YBLOCKS * it) * BM;
        const int m0n = (blockIdx.y + YBLOCKS * (it + 1)) * BM;

        float c[2][8][4];
        #pragma unroll
        for (int i = 0; i < 2; ++i)
            #pragma unroll
            for (int j = 0; j < 8; ++j)
                #pragma unroll
                for (int qq = 0; qq < 4; ++qq) c[i][j][qq] = 0.0f;

        auto half_mma = [&](const float* __restrict__ Ab, int koff) {
            #pragma unroll
            for (int kk = 0; kk < 8; ++kk) {
                const int k0 = kk * 8;
                const int kb = koff + k0;
                uint32_t a[2][4];
                #pragma unroll
                for (int i = 0; i < 2; ++i) {
                    int r = wm * 32 + i * 16 + g;
                    a[i][0] = f2tf32(Ab[r * LDA_F + k0 + t]);
                    a[i][1] = f2tf32(Ab[(r + 8) * LDA_F + k0 + t]);
                    a[i][2] = f2tf32(Ab[r * LDA_F + k0 + t + 4]);
                    a[i][3] = f2tf32(Ab[(r + 8) * LDA_F + k0 + t + 4]);
                }
                #pragma unroll
                for (int j = 0; j < 8; ++j) {
                    int d = wn * 64 + j * 8 + g;
                    uint32_t b0 = __float_as_uint(Bs[d * LDB_F + kb + t]);
                    uint32_t b1 = __float_as_uint(Bs[d * LDB_F + kb + t + 4]);
                    mma_tf32(c[0][j], a[0][0], a[0][1], a[0][2], a[0][3], b0, b1);
                    mma_tf32(c[1][j], a[1][0], a[1][1], a[1][2], a[1][3], b0, b1);
                }
            }
        };

        cp_wait<1>();
        __syncthreads();
        half_mma(A0, 0);
        __syncthreads();
        if (it < 1) issue_chunk(A0, m0n, 0);

        if (it < 1) cp_wait<1>(); else cp_wait<0>();
        __syncthreads();
        half_mma(A1, 64);

        float sacc[2][2] = {{0.f, 0.f}, {0.f, 0.f}};
        float qacc[2][2] = {{0.f, 0.f}, {0.f, 0.f}};
        #pragma unroll
        for (int i = 0; i < 2; ++i)
            #pragma unroll
            for (int j = 0; j < 8; ++j) {
                const float* cc = c[i][j];
                sacc[i][0] += cc[0] + cc[1];
                qacc[i][0] += cc[0] * cc[0] + cc[1] * cc[1];
                sacc[i][1] += cc[2] + cc[3];
                qacc[i][1] += cc[2] * cc[2] + cc[3] * cc[3];
            }
        #pragma unroll
        for (int i = 0; i < 2; ++i)
            #pragma unroll
            for (int s = 0; s < 2; ++s) {
                float sv = sacc[i][s], qv = qacc[i][s];
                sv += __shfl_xor_sync(0xffffffffu, sv, 1);
                sv += __shfl_xor_sync(0xffffffffu, sv, 2);
                qv += __shfl_xor_sync(0xffffffffu, qv, 1);
                qv += __shfl_xor_sync(0xffffffffu, qv, 2);
                if (t == 0) {
                    int r = wm * 32 + i * 16 + s * 8 + g;
                    Ps[r * 4 + wn] = sv;
                    Pq[r * 4 + wn] = qv;
                }
            }
        __syncthreads();
        if (it < 1) issue_chunk(A1, m0n, 1);

        if (tid < BM) {
            float sv = Ps[tid * 4 + 0] + Ps[tid * 4 + 1] + Ps[tid * 4 + 2] + Ps[tid * 4 + 3];
            float qv = Pq[tid * 4 + 0] + Pq[tid * 4 + 1] + Pq[tid * 4 + 2] + Pq[tid * 4 + 3];
            float mu  = sv * (1.0f / COUT);
            float var = qv * (1.0f / COUT) - mu * mu;
            Mu[tid] = mu;
            Rs[tid] = rsqrtf(var + LN_EPS);
        }
        __syncthreads();

        const size_t obase = ((size_t)p * NROWS + m0) * COUT;
        #pragma unroll
        for (int i = 0; i < 2; ++i) {
            int r0 = wm * 32 + i * 16 + g;
            float mu0 = Mu[r0],     rs0 = Rs[r0];
            float mu1 = Mu[r0 + 8], rs1 = Rs[r0 + 8];
            #pragma unroll
            for (int j = 0; j < 8; ++j) {
                int col = wn * 64 + j * 8 + 2 * t;
                float g0 = __ldg(&gamma[col]), g1 = __ldg(&gamma[col + 1]);
                float b0 = __ldg(&beta[col]),  b1 = __ldg(&beta[col + 1]);
                float2 v0, v1;
                v0.x = (c[i][j][0] - mu0) * rs0 * g0 + b0;
                v0.y = (c[i][j][1] - mu0) * rs0 * g1 + b1;
                v1.x = (c[i][j][2] - mu1) * rs1 * g0 + b0;
                v1.y = (c[i][j][3] - mu1) * rs1 * g1 + b1;
                *(float2*)&out[obase + (size_t)r0 * COUT + col]       = v0;
                *(float2*)&out[obase + (size_t)(r0 + 8) * COUT + col] = v1;
            }
        }
    }
#endif
}

extern "C" void kernel_launch(void* const* d_in, const int* in_sizes, int n_in,
                              void* d_out, int out_size)
{
    const float* x     = (const float*)d_in[0];
    const float* W     = (const float*)d_in[1];
    const float* gamma = (const float*)d_in[2];
    const float* beta  = (const float*)d_in[3];
    float* out = (float*)d_out;

    cudaFuncSetAttribute(fused_gemm_ln,
                         cudaFuncAttributeMaxDynamicSharedMemorySize, (int)TC_SMEM_BYTES);

    dim3 grid(P_PARTS, YBLOCKS);
    fused_gemm_ln<<<grid, NTHREADS, (int)TC_SMEM_BYTES>>>(x, W, gamma, beta, out);
}

// round 11
// speedup vs baseline: 1.3804x; 1.0633x over previous
#include <cuda_runtime.h>
#include <cstdint>

// x[62,8192,128] f32, W[62,256,128] f32, gamma[256], beta[256]
// out[62,8192,256] f32 = LayerNorm(x @ W^T) over the 256 dim.
//
// compute_103a path: tcgen05 kind::tf32 SS-mode, 2 CTAs/SM (104KB smem, 256 TMEM
// cols per CTA; alloc permit relinquished IMMEDIATELY so co-resident CTA can
// alloc too). A and B(=W) streamed via 2-slot cp.async rings (W re-reads = L2
// hits). Warps: 0-7 epilogue (2-pass streaming LDTM), 8-11 loaders, 12 MMA.
// Fallback (plain compute_103 PTX pass): compiles only, never runs on sm_103a.

#define P_PARTS 62
#define NROWS   8192
#define CIN     128
#define COUT    256
#define BM      128
#define YBLOCKS 32
#define ITERS   2
#define NTHREADS 416
#define EPI_T   256
#define LD_T    128
#define LN_EPS  1e-5f

#if defined(__CUDA_ARCH__) && (defined(__CUDA_ARCH_FEAT_SM103_ALL) || defined(__CUDA_ARCH_FEAT_SM100_ALL) || defined(__CUDA_ARCH_FEAT_SM101_ALL))
#define HAS_TCGEN05 1
#else
#define HAS_TCGEN05 0
#endif

// ---- smem layout (bytes) ----
#define TMEM_PTR_OFF 0
#define MB_A_FULL(s)  (16 + (s) * 8)     // count 128 (loader cp.async arrives)
#define MB_A_EMPTY(s) (32 + (s) * 8)     // count 1 (tcgen05.commit)
#define MB_B_FULL(s)  (48 + (s) * 8)     // count 128
#define MB_B_EMPTY(s) (64 + (s) * 8)     // count 1 (commit)
#define MB_D_FULL     80                 // count 1 (commit)
#define MB_D_EMPTY    88                 // count 256 (epilogue threads)
#define GS_OFF       128
#define BT_OFF       1152
#define PS_OFF       2176                // [2 parity][128 row][2 half] = 2KB
#define PQ_OFF       4224                // 2KB
#define A_OFF        8192                // 2 slots x 16KB (128 rows x 128B, K=32)
#define A_SLOT_BYTES 16384
#define B_OFF        (A_OFF + 2 * A_SLOT_BYTES)   // 2 slots x 32KB (256 x 128B, K=32)
#define B_SLOT_BYTES 32768
#define TC_SMEM_BYTES (B_OFF + 2 * B_SLOT_BYTES)  // 106496

// idesc kind::tf32: c=F32(1<<4), a=TF32(2<<7), b=TF32(2<<10), N/8<<17, M/16<<24
#define MMA_IDESC ((1u << 4) | (2u << 7) | (2u << 10) | ((COUT / 8) << 17) | ((BM / 16) << 24))

static constexpr uint64_t SMEM_DESC_BASE_SW128 =
    (uint64_t(2) << 61) | (uint64_t(1) << 46) | (uint64_t(64) << 32) | (uint64_t(1) << 16);
#define MAKE_SMEM_DESC(base_addr) \
    (SMEM_DESC_BASE_SW128 | ((uint64_t)((base_addr) >> 4) & 0x3FFF))
#define SMEM_SWIZZLE_128B(off) ((off) ^ (((off) >> 3) & 0x70))

// ---- fallback constants (compile-only on plain compute_103) ----
#define KC      64
#define LDA_F   68
#define LDB_F   132
#define FB_T    512

__device__ __forceinline__ uint32_t f2tf32(float f) {
    uint32_t r;
    asm volatile("cvt.rna.tf32.f32 %0, %1;" : "=r"(r) : "f"(f));
    return r;
}
__device__ __forceinline__ uint32_t smem_u32(const void* p) {
    uint32_t a;
    asm("{ .reg .u64 t; cvta.to.shared.u64 t, %1; cvt.u32.u64 %0, t; }" : "=r"(a) : "l"(p));
    return a;
}
__device__ __forceinline__ void cp16s(uint32_t dst_smem, const float* src) {
    asm volatile("cp.async.cg.shared.global [%0], [%1], 16;" :: "r"(dst_smem), "l"(src));
}

#if HAS_TCGEN05
__device__ __forceinline__ uint32_t elect_one() {
    uint32_t pred;
    asm volatile("{ .reg .pred p; elect.sync _|p, 0xFFFFFFFF; selp.b32 %0, 1, 0, p; }" : "=r"(pred));
    return pred;
}
#define MBARRIER_INIT(a, n) \
    asm volatile("mbarrier.init.shared.b64 [%0], %1;" :: "r"((uint32_t)(a)), "r"((uint32_t)(n)) : "memory")
#define MBARRIER_ARRIVE(a) \
    asm volatile("mbarrier.arrive.shared.b64 _, [%0];" :: "r"((uint32_t)(a)) : "memory")
#define CPASYNC_ARRIVE(a) \
    asm volatile("cp.async.mbarrier.arrive.noinc.shared.b64 [%0];" :: "r"((uint32_t)(a)) : "memory")
#define MBAR_WAIT(a, ph) do {                                              \
    uint32_t _m = (uint32_t)(a), _p = (uint32_t)(ph);                      \
    asm volatile(                                                          \
        "{\n\t.reg .pred P1;\n\t"                                          \
        "WL_%=:\n\t"                                                       \
        "mbarrier.try_wait.parity.acquire.cta.shared::cta.b64 P1, [%0], %1, 0x989680;\n\t" \
        "@P1 bra.uni WD_%=;\n\t"                                           \
        "bra.uni WL_%=;\n\t"                                               \
        "WD_%=:\n\t}"                                                      \
        :: "r"(_m), "r"(_p) : "memory");                                   \
} while (0)
#define MBAR_WAIT_RELAXED(a, ph) do {                                      \
    uint32_t _m = (uint32_t)(a), _p = (uint32_t)(ph);                      \
    asm volatile(                                                          \
        "{\n\t.reg .pred P1;\n\t"                                          \
        "WL_%=:\n\t"                                                       \
        "mbarrier.try_wait.parity.relaxed.cta.shared::cta.b64 P1, [%0], %1, 0x989680;\n\t" \
        "@P1 bra.uni WD_%=;\n\t"                                           \
        "bra.uni WL_%=;\n\t"                                               \
        "WD_%=:\n\t}"                                                      \
        :: "r"(_m), "r"(_p) : "memory");                                   \
} while (0)
#define FENCE_ASYNC() asm volatile("fence.proxy.async.shared::cta;" ::: "memory")
#define TCGEN05_ALLOC(sm, n) \
    asm volatile("tcgen05.alloc.cta_group::1.sync.aligned.shared::cta.b32 [%0], %1;" \
                 :: "r"((uint32_t)(sm)), "r"((uint32_t)(n)) : "memory")
#define TCGEN05_DEALLOC(t, n) \
    asm volatile("tcgen05.dealloc.cta_group::1.sync.aligned.b32 %0, %1;" :: "r"(t), "r"((uint32_t)(n)))
#define TCGEN05_RELINQ() \
    asm volatile("tcgen05.relinquish_alloc_permit.cta_group::1.sync.aligned;")
#define TCGEN05_COMMIT(mb) \
    asm volatile("tcgen05.commit.cta_group::1.mbarrier::arrive::one.shared::cluster.b64 [%0];" \
                 :: "r"((uint32_t)(mb)) : "memory")
#define TCGEN05_FENCE_AFTER()  asm volatile("tcgen05.fence::after_thread_sync;" ::: "memory")
#define TCGEN05_FENCE_BEFORE() asm volatile("tcgen05.fence::before_thread_sync;" ::: "memory")
#define TCGEN05_WAIT_LD() asm volatile("tcgen05.wait::ld.sync.aligned;" ::: "memory")

__device__ __forceinline__ void mma_tf32_ss(uint32_t d_tmem, uint64_t a_desc, uint64_t b_desc,
                                            uint32_t idesc, uint32_t enable) {
    asm volatile(
        "{\n\t.reg .pred p;\n\t"
        "setp.ne.u32 p, %4, 0;\n\t"
        "tcgen05.mma.cta_group::1.kind::tf32 [%0], %1, %2, %3, {%5, %5, %5, %5}, p;\n\t}"
        :: "r"(d_tmem), "l"(a_desc), "l"(b_desc), "r"(idesc), "r"(enable), "r"(0u)
        : "memory");
}

#define TCGEN05_LD_X32(r, addr)                                                     \
    asm volatile(                                                                   \
        "tcgen05.ld.sync.aligned.32x32b.x32.b32 "                                   \
        "{%0, %1, %2, %3, %4, %5, %6, %7, "                                         \
        " %8, %9, %10, %11, %12, %13, %14, %15, "                                   \
        " %16, %17, %18, %19, %20, %21, %22, %23, "                                 \
        " %24, %25, %26, %27, %28, %29, %30, %31}, [%32];"                          \
        : "=r"((r)[0]),  "=r"((r)[1]),  "=r"((r)[2]),  "=r"((r)[3]),                \
          "=r"((r)[4]),  "=r"((r)[5]),  "=r"((r)[6]),  "=r"((r)[7]),                \
          "=r"((r)[8]),  "=r"((r)[9]),  "=r"((r)[10]), "=r"((r)[11]),               \
          "=r"((r)[12]), "=r"((r)[13]), "=r"((r)[14]), "=r"((r)[15]),               \
          "=r"((r)[16]), "=r"((r)[17]), "=r"((r)[18]), "=r"((r)[19]),               \
          "=r"((r)[20]), "=r"((r)[21]), "=r"((r)[22]), "=r"((r)[23]),               \
          "=r"((r)[24]), "=r"((r)[25]), "=r"((r)[26]), "=r"((r)[27]),               \
          "=r"((r)[28]), "=r"((r)[29]), "=r"((r)[30]), "=r"((r)[31])                \
        : "r"(addr))

#define NAMED_BAR(id, n) asm volatile("bar.sync %0, %1;" :: "r"(id), "r"(n) : "memory")
#else
__device__ __forceinline__ void cp_commit() {
    asm volatile("cp.async.commit_group;" ::: "memory");
}
template <int N>
__device__ __forceinline__ void cp_wait() {
    asm volatile("cp.async.wait_group %0;" :: "n"(N) : "memory");
}
__device__ __forceinline__ void mma_tf32(float c[4],
                                         uint32_t a0, uint32_t a1, uint32_t a2, uint32_t a3,
                                         uint32_t b0, uint32_t b1) {
    asm volatile(
        "mma.sync.aligned.m16n8k8.row.col.f32.tf32.tf32.f32 "
        "{%0,%1,%2,%3}, {%4,%5,%6,%7}, {%8,%9}, {%0,%1,%2,%3};"
        : "+f"(c[0]), "+f"(c[1]), "+f"(c[2]), "+f"(c[3])
        : "r"(a0), "r"(a1), "r"(a2), "r"(a3), "r"(b0), "r"(b1));
}
#endif

extern __shared__ char smem_raw[];

__global__ void __launch_bounds__(NTHREADS, 2)
fused_gemm_ln(const float* __restrict__ x, const float* __restrict__ W,
              const float* __restrict__ gamma, const float* __restrict__ beta,
              float* __restrict__ out)
{
#if HAS_TCGEN05
    char* smem = smem_raw;
    const uint32_t sb = smem_u32(smem);
    const int tid  = threadIdx.x;
    const int wid  = tid >> 5;
    const int lane = tid & 31;
    const int p    = blockIdx.x;

    if (wid == 12) {
        TCGEN05_ALLOC(sb + TMEM_PTR_OFF, 256);
        TCGEN05_RELINQ();    // release permit NOW so the co-resident CTA can alloc
    }
    if (tid == 0) {
        #pragma unroll
        for (int s = 0; s < 2; ++s) {
            MBARRIER_INIT(sb + MB_A_FULL(s), LD_T);
            MBARRIER_INIT(sb + MB_A_EMPTY(s), 1);
            MBARRIER_INIT(sb + MB_B_FULL(s), LD_T);
            MBARRIER_INIT(sb + MB_B_EMPTY(s), 1);
        }
        MBARRIER_INIT(sb + MB_D_FULL, 1);
        MBARRIER_INIT(sb + MB_D_EMPTY, EPI_T);
    }
    if (tid < COUT) {
        ((float*)(smem + GS_OFF))[tid] = gamma[tid];
        ((float*)(smem + BT_OFF))[tid] = beta[tid];
    }
    __syncthreads();

    uint32_t tmem_base;
    asm volatile("ld.shared.b32 %0, [%1];" : "=r"(tmem_base) : "r"(sb + TMEM_PTR_OFF));

    const float* xp = x + (size_t)p * NROWS * CIN;
    const float* wp = W + (size_t)p * COUT * CIN;

    if (wid >= 8 && wid < 12) {
        // =================== loader warps (A + B cp.async rings) ===================
        const int ltid = tid - EPI_T;            // 0..127
        #pragma unroll 1
        for (int c = 0; c < ITERS * 4; ++c) {
            const int it = c >> 2;
            const int kc = c & 3;
            const int s  = c & 1;
            const int k  = c >> 1;               // per-slot use count
            const int pe = 1 ^ (k & 1);          // producer-reclaim parity
            const int m0 = (blockIdx.y + YBLOCKS * it) * BM;

            MBAR_WAIT(sb + MB_A_EMPTY(s), pe);
            {
                const uint32_t abase = sb + A_OFF + s * A_SLOT_BYTES;
                #pragma unroll
                for (int i = 0; i < 8; ++i) {
                    int idx = ltid + i * LD_T;   // 0..1023 f4
                    int row = idx >> 3;
                    int f4  = idx & 7;
                    uint32_t off = SMEM_SWIZZLE_128B((uint32_t)(row * 128 + f4 * 16));
                    cp16s(abase + off, xp + (size_t)(m0 + row) * CIN + kc * 32 + f4 * 4);
                }
                CPASYNC_ARRIVE(sb + MB_A_FULL(s));
            }
            MBAR_WAIT(sb + MB_B_EMPTY(s), pe);
            {
                const uint32_t bbase = sb + B_OFF + s * B_SLOT_BYTES;
                #pragma unroll
                for (int i = 0; i < 16; ++i) {
                    int idx = ltid + i * LD_T;   // 0..2047 f4
                    int row = idx >> 3;          // 0..255
                    int f4  = idx & 7;
                    uint32_t off = SMEM_SWIZZLE_128B((uint32_t)(row * 128 + f4 * 16));
                    cp16s(bbase + off, wp + (size_t)row * CIN + kc * 32 + f4 * 4);
                }
                CPASYNC_ARRIVE(sb + MB_B_FULL(s));
            }
        }
    } else if (wid == 12) {
        // =================== MMA warp ===================
        if (elect_one()) {
            #pragma unroll 1
            for (int it = 0; it < ITERS; ++it) {
                MBAR_WAIT_RELAXED(sb + MB_D_EMPTY, 1 ^ (it & 1));
                #pragma unroll 1
                for (int kc = 0; kc < 4; ++kc) {
                    const int c = it * 4 + kc;
                    const int s = c & 1;
                    const int pf = (c >> 1) & 1;     // consumer parity
                    MBAR_WAIT_RELAXED(sb + MB_A_FULL(s), pf);
                    MBAR_WAIT_RELAXED(sb + MB_B_FULL(s), pf);
                    FENCE_ASYNC();   // cp.async writes -> async-proxy visibility
                    uint64_t a_base = MAKE_SMEM_DESC(sb + A_OFF + s * A_SLOT_BYTES);
                    uint64_t b_base = MAKE_SMEM_DESC(sb + B_OFF + s * B_SLOT_BYTES);
                    #pragma unroll
                    for (int ks = 0; ks < 4; ++ks) {
                        mma_tf32_ss(tmem_base, a_base + ks * 2, b_base + ks * 2,
                                    MMA_IDESC, (uint32_t)(kc | ks));
                    }
                    TCGEN05_COMMIT(sb + MB_A_EMPTY(s));
                    TCGEN05_COMMIT(sb + MB_B_EMPTY(s));
                }
                TCGEN05_COMMIT(sb + MB_D_FULL);
            }
        }
    } else {
        // =================== epilogue warps (0-7), streaming 2-pass ===================
        const int h   = wid >> 2;                // column half (128 cols)
        const int sub = wid & 3;                 // TMEM subpartition
        const int row = sub * 32 + lane;
        float* Ps = (float*)(smem + PS_OFF);
        float* Pq = (float*)(smem + PQ_OFF);
        const float* Gs = (const float*)(smem + GS_OFF);
        const float* Bt = (const float*)(smem + BT_OFF);
        #pragma unroll 1
        for (int it = 0; it < ITERS; ++it) {
            const int par = it & 1;
            MBAR_WAIT(sb + MB_D_FULL, par);
            TCGEN05_FENCE_AFTER();
            const uint32_t dt = tmem_base + h * 128;

            // pass 1: stats
            float sv = 0.f, qv = 0.f;
            #pragma unroll 1
            for (int st = 0; st < 4; ++st) {
                uint32_t d[32];
                TCGEN05_LD_X32(d, dt + st * 32);
                TCGEN05_WAIT_LD();
                #pragma unroll
                for (int j = 0; j < 32; ++j) {
                    float f = __uint_as_float(d[j]);
                    sv += f;
                    qv += f * f;
                }
            }
            Ps[par * 256 + row * 2 + h] = sv;
            Pq[par * 256 + row * 2 + h] = qv;
            NAMED_BAR(1, EPI_T);
            float tot = Ps[par * 256 + row * 2] + Ps[par * 256 + row * 2 + 1];
            float qt  = Pq[par * 256 + row * 2] + Pq[par * 256 + row * 2 + 1];
            float mu  = tot * (1.0f / COUT);
            float var = qt * (1.0f / COUT) - mu * mu;
            float rs  = rsqrtf(var + LN_EPS);

            // pass 2: normalize + store
            const int m0 = (blockIdx.y + YBLOCKS * it) * BM;
            float* orow = out + ((size_t)p * NROWS + m0 + row) * COUT + h * 128;
            #pragma unroll 1
            for (int st = 0; st < 4; ++st) {
                uint32_t d[32];
                TCGEN05_LD_X32(d, dt + st * 32);
                TCGEN05_WAIT_LD();
                const int cb = h * 128 + st * 32;
                #pragma unroll
                for (int k = 0; k < 4; ++k) {
                    float4 g4 = *(const float4*)&Gs[cb + k * 8];
                    float4 g5 = *(const float4*)&Gs[cb + k * 8 + 4];
                    float4 b4 = *(const float4*)&Bt[cb + k * 8];
                    float4 b5 = *(const float4*)&Bt[cb + k * 8 + 4];
                    float4 o0, o1;
                    o0.x = (__uint_as_float(d[k*8+0]) - mu) * rs * g4.x + b4.x;
                    o0.y = (__uint_as_float(d[k*8+1]) - mu) * rs * g4.y + b4.y;
                    o0.z = (__uint_as_float(d[k*8+2]) - mu) * rs * g4.z + b4.z;
                    o0.w = (__uint_as_float(d[k*8+3]) - mu) * rs * g4.w + b4.w;
                    o1.x = (__uint_as_float(d[k*8+4]) - mu) * rs * g5.x + b5.x;
                    o1.y = (__uint_as_float(d[k*8+5]) - mu) * rs * g5.y + b5.y;
                    o1.z = (__uint_as_float(d[k*8+6]) - mu) * rs * g5.z + b5.z;
                    o1.w = (__uint_as_float(d[k*8+7]) - mu) * rs * g5.w + b5.w;
                    *(float4*)&orow[st * 32 + k * 8]     = o0;
                    *(float4*)&orow[st * 32 + k * 8 + 4] = o1;
                }
            }
            TCGEN05_FENCE_BEFORE();
            MBARRIER_ARRIVE(sb + MB_D_EMPTY);
        }
    }

    __syncthreads();
    if (wid == 12) {
        TCGEN05_DEALLOC(tmem_base, 256);
    }
#else
    // ============ fallback: cp.async + mma.sync (compile-only on compute_103) ============
    if (threadIdx.x >= FB_T) return;
    float* smem = (float*)smem_raw;
    float* Bs = smem;
    float* A0 = Bs + COUT * LDB_F;
    float* A1 = A0 + BM * LDA_F;
    float* Ps = A1 + BM * LDA_F;
    float* Pq = Ps + 128 * 4;
    float* Mu = Pq + 128 * 4;
    float* Rs = Mu + 128;

    const int tid  = threadIdx.x;
    const int warp = tid >> 5;
    const int lane = tid & 31;
    const int wm = warp >> 2;
    const int wn = warp & 3;
    const int g  = lane >> 2;
    const int t  = lane & 3;
    const int p  = blockIdx.x;

    const float* xp = x + (size_t)p * NROWS * CIN;

    auto issue_chunk = [&](float* buf, int m0, int kc) {
        #pragma unroll
        for (int ii = 0; ii < 4; ++ii) {
            int idx = tid + ii * FB_T;
            int row = idx >> 4;
            int c4  = idx & 15;
            cp16s((uint32_t)__cvta_generic_to_shared(&buf[row * LDA_F + c4 * 4]),
                  xp + ((size_t)(m0 + row)) * CIN + kc * KC + c4 * 4);
        }
        cp_commit();
    };

    {
        const int m0 = blockIdx.y * BM;
        issue_chunk(A0, m0, 0);
        issue_chunk(A1, m0, 1);
    }
    {
        const float4* wp4 = (const float4*)(W + (size_t)p * COUT * CIN);
        #pragma unroll
        for (int ii = 0; ii < (COUT * CIN / 4) / FB_T; ++ii) {
            int idx = tid + ii * FB_T;
            int row = idx >> 5;
            int c4  = idx & 31;
            float4 v = wp4[idx];
            float* dst = &Bs[row * LDB_F + c4 * 4];
            dst[0] = __uint_as_float(f2tf32(v.x));
            dst[1] = __uint_as_float(f2tf32(v.y));
            dst[2] = __uint_as_float(f2tf32(v.z));
            dst[3] = __uint_as_float(f2tf32(v.w));
        }
    }

    #pragma unroll
    for (int it = 0; it < 2; ++it) {
        const int m0  = (blockIdx.y + YBLOCKS * it) * BM;
        const int m0n = (blockIdx.y + YBLOCKS * (it + 1)) * BM;

        float c[2][8][4];
        #pragma unroll
        for (int i = 0; i < 2; ++i)
            #pragma unroll
            for (int j = 0; j < 8; ++j)
                #pragma unroll
                for (int qq = 0; qq < 4; ++qq) c[i][j][qq] = 0.0f;

        auto half_mma = [&](const float* __restrict__ Ab, int koff) {
            #pragma unroll
            for (int kk = 0; kk < 8; ++kk) {
                const int k0 = kk * 8;
                const int kb = koff + k0;
                uint32_t a[2][4];
                #pragma unroll
                for (int i = 0; i < 2; ++i) {
                    int r = wm * 32 + i * 16 + g;
                    a[i][0] = f2tf32(Ab[r * LDA_F + k0 + t]);
                    a[i][1] = f2tf32(Ab[(r + 8) * LDA_F + k0 + t]);
                    a[i][2] = f2tf32(Ab[r * LDA_F + k0 + t + 4]);
                    a[i][3] = f2tf32(Ab[(r + 8) * LDA_F + k0 + t + 4]);
                }
                #pragma unroll
                for (int j = 0; j < 8; ++j) {
                    int d = wn * 64 + j * 8 + g;
                    uint32_t b0 = __float_as_uint(Bs[d * LDB_F + kb + t]);
                    uint32_t b1 = __float_as_uint(Bs[d * LDB_F + kb + t + 4]);
                    mma_tf32(c[0][j], a[0][0], a[0][1], a[0][2], a[0][3], b0, b1);
                    mma_tf32(c[1][j], a[1][0], a[1][1], a[1][2], a[1][3], b0, b1);
                }
            }
        };

        cp_wait<1>();
        __syncthreads();
        half_mma(A0, 0);
        __syncthreads();
        if (it < 1) issue_chunk(A0, m0n, 0);

        if (it < 1) cp_wait<1>(); else cp_wait<0>();
        __syncthreads();
        half_mma(A1, 64);

        float sacc[2][2] = {{0.f, 0.f}, {0.f, 0.f}};
        float qacc[2][2] = {{0.f, 0.f}, {0.f, 0.f}};
        #pragma unroll
        for (int i = 0; i < 2; ++i)
            #pragma unroll
            for (int j = 0; j < 8; ++j) {
                const float* cc = c[i][j];
                sacc[i][0] += cc[0] + cc[1];
                qacc[i][0] += cc[0] * cc[0] + cc[1] * cc[1];
                sacc[i][1] += cc[2] + cc[3];
                qacc[i][1] += cc[2] * cc[2] + cc[3] * cc[3];
            }
        #pragma unroll
        for (int i = 0; i < 2; ++i)
            #pragma unroll
            for (int s = 0; s < 2; ++s) {
                float sv = sacc[i][s], qv = qacc[i][s];
                sv += __shfl_xor_sync(0xffffffffu, sv, 1);
                sv += __shfl_xor_sync(0xffffffffu, sv, 2);
                qv += __shfl_xor_sync(0xffffffffu, qv, 1);
                qv += __shfl_xor_sync(0xffffffffu, qv, 2);
                if (t == 0) {
                    int r = wm * 32 + i * 16 + s * 8 + g;
                    Ps[r * 4 + wn] = sv;
                    Pq[r * 4 + wn] = qv;
                }
            }
        __syncthreads();
        if (it < 1) issue_chunk(A1, m0n, 1);

        if (tid < BM) {
            float sv = Ps[tid * 4 + 0] + Ps[tid * 4 + 1] + Ps[tid * 4 + 2] + Ps[tid * 4 + 3];
            float qv = Pq[tid * 4 + 0] + Pq[tid * 4 + 1] + Pq[tid * 4 + 2] + Pq[tid * 4 + 3];
            float mu  = sv * (1.0f / COUT);
            float var = qv * (1.0f / COUT) - mu * mu;
            Mu[tid] = mu;
            Rs[tid] = rsqrtf(var + LN_EPS);
        }
        __syncthreads();

        const size_t obase = ((size_t)p * NROWS + m0) * COUT;
        #pragma unroll
        for (int i = 0; i < 2; ++i) {
            int r0 = wm * 32 + i * 16 + g;
            float mu0 = Mu[r0],     rs0 = Rs[r0];
            float mu1 = Mu[r0 + 8], rs1 = Rs[r0 + 8];
            #pragma unroll
            for (int j = 0; j < 8; ++j) {
                int col = wn * 64 + j * 8 + 2 * t;
                float g0 = __ldg(&gamma[col]), g1 = __ldg(&gamma[col + 1]);
                float b0 = __ldg(&beta[col]),  b1 = __ldg(&beta[col + 1]);
                float2 v0, v1;
                v0.x = (c[i][j][0] - mu0) * rs0 * g0 + b0;
                v0.y = (c[i][j][1] - mu0) * rs0 * g1 + b1;
                v1.x = (c[i][j][2] - mu1) * rs1 * g0 + b0;
                v1.y = (c[i][j][3] - mu1) * rs1 * g1 + b1;
                *(float2*)&out[obase + (size_t)r0 * COUT + col]       = v0;
                *(float2*)&out[obase + (size_t)(r0 + 8) * COUT + col] = v1;
            }
        }
    }
#endif
}

extern "C" void kernel_launch(void* const* d_in, const int* in_sizes, int n_in,
                              void* d_out, int out_size)
{
    const float* x     = (const float*)d_in[0];
    const float* W     = (const float*)d_in[1];
    const float* gamma = (const float*)d_in[2];
    const float* beta  = (const float*)d_in[3];
    float* out = (float*)d_out;

    cudaFuncSetAttribute(fused_gemm_ln,
                         cudaFuncAttributeMaxDynamicSharedMemorySize, (int)TC_SMEM_BYTES);

    dim3 grid(P_PARTS, YBLOCKS);
    fused_gemm_ln<<<grid, NTHREADS, (int)TC_SMEM_BYTES>>>(x, W, gamma, beta, out);
}